// round 1
// baseline (speedup 1.0000x reference)
#include <cuda_runtime.h>
#include <stdint.h>

// SPD Frechet mean via per-block parallel Jacobi eigensolver.
// One block per batch element (512 blocks). All work in shared memory.
//
// Per step n = 1..15 (carry M in buffer A):
//   eigh(M) = (e, V)          [Jacobi #1, Vt = V^T accumulated]
//   Y  = Vt * X * Vt^T
//   S' = diag(e^-1/2) Y diag(e^-1/2)
//   eigh(S') = (f, U)         [Jacobi #2, Ut accumulated]
//   G  = Ut^T diag(f^t) Ut
//   K  = diag(e^1/2) G diag(e^1/2)
//   M' = Vt^T K Vt
// This is algebraically identical to the reference scan step.

#define TPB 256
#define STRIDE 66   // 64 + 2 pad: float2-aligned rows, 2-way-conflict columns

struct SmemLayout {
    float A [64 * STRIDE];   // work matrix / M carry
    float Vt[64 * STRIDE];   // V^T accumulator (eigh #1)
    float Ut[64 * STRIDE];   // U^T accumulator (eigh #2)
    float B1[64 * STRIDE];   // X / G / K
    float T1[64 * STRIDE];   // matmul temp
    float es[64], eis[64], ft[64];
    float csc[32], css[32];
    int   pp[32], qq[32];
    float red[18];
    float tvals[16];
};

__device__ __forceinline__ int mod63(int v) { return (v >= 63) ? v - 63 : v; }

__device__ void load_mat64(const float* __restrict__ g, float* __restrict__ s) {
    for (int id = threadIdx.x; id < 2048; id += TPB) {
        int i = id >> 5, jj = id & 31;
        reinterpret_cast<float2*>(s + i * STRIDE)[jj] =
            reinterpret_cast<const float2*>(g)[id];
    }
}

// C = op(A) * diag(d?) * op(B), 64x64, all smem with STRIDE rows.
// TA: a(i,k) = A[k][i] if 1 else A[i][k].  TB: b(k,j) = B[j][k] if 1 else B[k][j].
template <int TA, int TB, int USE_D>
__device__ void mm64(const float* __restrict__ A, const float* __restrict__ B,
                     float* __restrict__ C, const float* __restrict__ d) {
    const int tid = threadIdx.x;
    const int r0 = (tid >> 4) * 4;
    const int c0 = (tid & 15) * 4;
    float acc[4][4] = {};
    for (int k = 0; k < 64; k++) {
        float av[4], bv[4];
#pragma unroll
        for (int i = 0; i < 4; i++)
            av[i] = TA ? A[k * STRIDE + (r0 + i)] : A[(r0 + i) * STRIDE + k];
#pragma unroll
        for (int j = 0; j < 4; j++)
            bv[j] = TB ? B[(c0 + j) * STRIDE + k] : B[k * STRIDE + (c0 + j)];
        if (USE_D) {
            float dk = d[k];
#pragma unroll
            for (int j = 0; j < 4; j++) bv[j] *= dk;
        }
#pragma unroll
        for (int i = 0; i < 4; i++)
#pragma unroll
            for (int j = 0; j < 4; j++)
                acc[i][j] += av[i] * bv[j];
    }
#pragma unroll
    for (int i = 0; i < 4; i++)
#pragma unroll
        for (int j = 0; j < 4; j++)
            C[(r0 + i) * STRIDE + (c0 + j)] = acc[i][j];
}

// Parallel cyclic Jacobi eigensolver. On exit: A ~ diagonal (eigenvalues on
// diag), Vt = V^T so that  M = Vt^T * diag(A) * Vt.
__device__ void jacobi64(float* __restrict__ A, float* __restrict__ Vt,
                         SmemLayout* sm) {
    const int tid = threadIdx.x;
    // Vt = I
    for (int id = tid; id < 64 * 64; id += TPB) {
        int i = id >> 6, j = id & 63;
        Vt[i * STRIDE + j] = (i == j) ? 1.f : 0.f;
    }
    __syncthreads();

    for (int sweep = 0; sweep < 12; sweep++) {
        for (int r = 0; r < 63; r++) {
            // ---- angle phase: 32 disjoint pairs (circle tournament order)
            if (tid < 32) {
                int k = tid;
                int p = (k == 0) ? 0 : (mod63(k - 1 + r) + 1);
                int q = mod63(62 - k + r) + 1;
                sm->pp[k] = p; sm->qq[k] = q;
                float app = A[p * STRIDE + p];
                float aqq = A[q * STRIDE + q];
                float apq = A[p * STRIDE + q];
                float c = 1.f, s = 0.f;
                if (fabsf(apq) > 1e-30f) {
                    float th = (aqq - app) / (2.f * apq);
                    float t  = 1.f / (fabsf(th) + sqrtf(th * th + 1.f));
                    if (th < 0.f) t = -t;
                    c = 1.f / sqrtf(t * t + 1.f);
                    s = t * c;
                }
                sm->csc[k] = c; sm->css[k] = s;
            }
            __syncthreads();

            // ---- phase 1: row rotations of A (Jt*A) and Vt (Jt*Vt), float2
#pragma unroll
            for (int it = 0; it < 8; it++) {
                int id = tid + it * TPB;          // 0..2047
                int matSel = id >> 10;
                int rem = id & 1023;
                int k = rem >> 5, jj = rem & 31;
                int p = sm->pp[k], q = sm->qq[k];
                float c = sm->csc[k], s = sm->css[k];
                float* base = matSel ? Vt : A;
                float2* rp = reinterpret_cast<float2*>(base + p * STRIDE);
                float2* rq = reinterpret_cast<float2*>(base + q * STRIDE);
                float2 ap = rp[jj], aq = rq[jj];
                float2 np, nq;
                np.x = c * ap.x - s * aq.x;  np.y = c * ap.y - s * aq.y;
                nq.x = s * ap.x + c * aq.x;  nq.y = s * ap.y + c * aq.y;
                rp[jj] = np;  rq[jj] = nq;
            }
            __syncthreads();

            // ---- phase 2: column rotations of A (A*J)
#pragma unroll
            for (int it = 0; it < 8; it++) {
                int id = tid + it * TPB;          // 0..2047
                int k = id >> 6, i = id & 63;
                int p = sm->pp[k], q = sm->qq[k];
                float c = sm->csc[k], s = sm->css[k];
                float ap = A[i * STRIDE + p], aq = A[i * STRIDE + q];
                A[i * STRIDE + p] = c * ap - s * aq;
                A[i * STRIDE + q] = s * ap + c * aq;
            }
            __syncthreads();
        }

        // ---- convergence check (off-diag Frobenius vs total)
        float off = 0.f, dg = 0.f;
        for (int id = tid; id < 64 * 64; id += TPB) {
            int i = id >> 6, j = id & 63;
            float v = A[i * STRIDE + j];
            if (i == j) dg += v * v; else off += v * v;
        }
#pragma unroll
        for (int o = 16; o; o >>= 1) {
            off += __shfl_xor_sync(0xffffffffu, off, o);
            dg  += __shfl_xor_sync(0xffffffffu, dg,  o);
        }
        if ((tid & 31) == 0) {
            sm->red[(tid >> 5) * 2]     = off;
            sm->red[(tid >> 5) * 2 + 1] = dg;
        }
        __syncthreads();
        if (tid == 0) {
            float o2 = 0.f, d2 = 0.f;
            for (int w = 0; w < 8; w++) { o2 += sm->red[2 * w]; d2 += sm->red[2 * w + 1]; }
            sm->red[16] = o2;
            sm->red[17] = o2 + d2;
        }
        __syncthreads();
        float offT = sm->red[16], froT = sm->red[17];
        __syncthreads();
        if (offT <= 1e-13f * froT) break;
    }
}

__global__ void __launch_bounds__(TPB, 2)
spd_frechet_kernel(const float* __restrict__ x, const float* __restrict__ wm,
                   float* __restrict__ out) {
    extern __shared__ __align__(16) char smem_raw[];
    SmemLayout* sm = reinterpret_cast<SmemLayout*>(smem_raw);
    const int b = blockIdx.x;
    const int tid = threadIdx.x;

    // t_n = w_n / cumsum(w)_n  with  w = wm^2 (normalization cancels)
    if (tid == 0) {
        float cum = 0.f;
        for (int n = 0; n < 16; n++) {
            float w = wm[n] * wm[n];
            cum += w;
            sm->tvals[n] = w / cum;
        }
    }

    const float* xb = x + (size_t)b * 16 * 4096;
    load_mat64(xb, sm->A);                 // M0 = x[b, 0]
    __syncthreads();

    for (int n = 1; n < 16; n++) {
        // ---- eigh(M): A -> diag(e), Vt
        jacobi64(sm->A, sm->Vt, sm);
        if (tid < 64) {
            float e = fmaxf(sm->A[tid * STRIDE + tid], 1e-10f);
            float se = sqrtf(e);
            sm->es[tid]  = se;
            sm->eis[tid] = 1.f / se;
        }
        // ---- X into B1
        load_mat64(xb + (size_t)n * 4096, sm->B1);
        __syncthreads();

        // Y = Vt * X * Vt^T
        mm64<0, 0, 0>(sm->Vt, sm->B1, sm->T1, nullptr);
        __syncthreads();
        mm64<0, 1, 0>(sm->T1, sm->Vt, sm->A, nullptr);
        __syncthreads();

        // S' = diag(eis) Y diag(eis)
        for (int id = tid; id < 4096; id += TPB) {
            int i = id >> 6, j = id & 63;
            sm->A[i * STRIDE + j] *= sm->eis[i] * sm->eis[j];
        }
        __syncthreads();

        // ---- eigh(S'): A -> diag(f), Ut
        jacobi64(sm->A, sm->Ut, sm);
        float tn = sm->tvals[n];
        if (tid < 64) {
            float f = fmaxf(sm->A[tid * STRIDE + tid], 1e-10f);
            sm->ft[tid] = exp2f(tn * log2f(f));
        }
        __syncthreads();

        // G = Ut^T diag(f^t) Ut
        mm64<1, 0, 1>(sm->Ut, sm->Ut, sm->B1, sm->ft);
        __syncthreads();
        // K = diag(es) G diag(es)
        for (int id = tid; id < 4096; id += TPB) {
            int i = id >> 6, j = id & 63;
            sm->B1[i * STRIDE + j] *= sm->es[i] * sm->es[j];
        }
        __syncthreads();
        // M' = Vt^T K Vt
        mm64<1, 0, 0>(sm->Vt, sm->B1, sm->T1, nullptr);
        __syncthreads();
        mm64<0, 0, 0>(sm->T1, sm->Vt, sm->A, nullptr);
        __syncthreads();
    }

    // write M (shape: out[b, 0, i, j])
    float* ob = out + (size_t)b * 4096;
    for (int id = tid; id < 2048; id += TPB) {
        int i = id >> 5, jj = id & 31;
        reinterpret_cast<float2*>(ob)[id] =
            reinterpret_cast<const float2*>(sm->A + i * STRIDE)[jj];
    }
}

extern "C" void kernel_launch(void* const* d_in, const int* in_sizes, int n_in,
                              void* d_out, int out_size) {
    (void)in_sizes; (void)n_in; (void)out_size;
    const float* x  = (const float*)d_in[0];
    const float* wm = (const float*)d_in[1];
    float* out = (float*)d_out;

    int smem = (int)sizeof(SmemLayout);
    cudaFuncSetAttribute(spd_frechet_kernel,
                         cudaFuncAttributeMaxDynamicSharedMemorySize, smem);
    spd_frechet_kernel<<<512, TPB, smem>>>(x, wm, out);
}

// round 6
// speedup vs baseline: 1.7286x; 1.7286x over previous
#include <cuda_runtime.h>
#include <stdint.h>

// SPD Frechet mean, one block per batch element (512 blocks).
//
// Eigensolver: one-sided Jacobi SVD on a FACTOR G with M = G^T G.
// Columns of G are orthogonalized by Givens rotations (register-resident,
// tournament exchange through smem slots, double-buffered, 1 sync/round).
// At convergence G*J = Hhat*diag(sigma):  sigma = sqrt(eigvals of M), and
// eigenvectors  V^T = diag(1/sigma) * Hhat^T * G  (no accumulator needed).
//
// Step n (carry Ft = F^T row-major: rows of Ft = columns of F, M = F^T F):
//   jacobi(Ft) -> Ht1, sigma
//   Vt  = diag(1/sigma) Ht1 Ft^T                     (= V^T)
//   L   = chol(X_n)
//   Ct  = diag(eis) Vt L                             (S' = C^T C in eigenbasis)
//   jacobi(Ct) -> Ht2, tau ; f = tau^2
//   U't = diag(1/tau) Ht2 Ct^T                       (= U'^T)
//   Ft' = V diag(es) U' diag(f^{t/2})                (middle-diag matmul)
// Output: M = Ft Ft^T.

#define TPB 256
#define MSTR 66          // row stride (floats) of 64x64 matrices
#define SLOTF2 72        // Jacobi slot stride in float2
#define COLF2 34         // second column offset within slot (float2)

struct Smem {
    float M0[64 * MSTR];           // Ft
    float M1[64 * MSTR];           // Vt
    float M2[64 * MSTR];           // X / L, later U't
    float M3[64 * MSTR];           // Ct
    float2 Bj[2][32 * SLOTF2];     // Jacobi double buffer (Ht aliases idle half)
    float ev[64], isig[64], es[64], eis[64], itau[64], ft2[64];
    float tvals[16], red[16];
};

__device__ __forceinline__ float2 ffma2(float2 a, float2 b, float2 c) {
    float2 r;
    asm("fma.rn.f32x2 %0, %1, %2, %3;"
        : "=l"(*reinterpret_cast<unsigned long long*>(&r))
        : "l"(*reinterpret_cast<unsigned long long*>(&a)),
          "l"(*reinterpret_cast<unsigned long long*>(&b)),
          "l"(*reinterpret_cast<unsigned long long*>(&c)));
    return r;
}
__device__ __forceinline__ float2 fmul2(float2 a, float2 b) {
    float2 r;
    asm("mul.rn.f32x2 %0, %1, %2;"
        : "=l"(*reinterpret_cast<unsigned long long*>(&r))
        : "l"(*reinterpret_cast<unsigned long long*>(&a)),
          "l"(*reinterpret_cast<unsigned long long*>(&b)));
    return r;
}

__device__ void load_mat64(const float* __restrict__ g, float* __restrict__ s) {
    for (int id = threadIdx.x; id < 2048; id += TPB) {
        int i = id >> 5, jj = id & 31;
        reinterpret_cast<float2*>(s + i * MSTR)[jj] =
            reinterpret_cast<const float2*>(g)[id];
    }
}

// C[r][c] = dr[r]? * dc[c]? * sum_k a(r,k) * dm[k]? * b(k,c)
// TA: a(r,k)=A[k][r] else A[r][k].  TB: b(k,c)=B[c][k] else B[k][c].
template <int TA, int TB, int MD, int RS, int CS>
__device__ void mm64(const float* __restrict__ A, const float* __restrict__ B,
                     float* __restrict__ C, const float* __restrict__ dm,
                     const float* __restrict__ dr, const float* __restrict__ dc) {
    const int tid = threadIdx.x;
    const int r0 = (tid >> 4) * 4;
    const int c0 = (tid & 15) * 4;
    float acc[4][4] = {};
    for (int k = 0; k < 64; k++) {
        float av[4], bv[4];
#pragma unroll
        for (int i = 0; i < 4; i++)
            av[i] = TA ? A[k * MSTR + (r0 + i)] : A[(r0 + i) * MSTR + k];
#pragma unroll
        for (int j = 0; j < 4; j++)
            bv[j] = TB ? B[(c0 + j) * MSTR + k] : B[k * MSTR + (c0 + j)];
        if (MD) {
            float dk = dm[k];
#pragma unroll
            for (int j = 0; j < 4; j++) bv[j] *= dk;
        }
#pragma unroll
        for (int i = 0; i < 4; i++)
#pragma unroll
            for (int j = 0; j < 4; j++)
                acc[i][j] += av[i] * bv[j];
    }
    float rs[4] = {1.f, 1.f, 1.f, 1.f}, cs[4] = {1.f, 1.f, 1.f, 1.f};
    if (RS) {
#pragma unroll
        for (int i = 0; i < 4; i++) rs[i] = dr[r0 + i];
    }
    if (CS) {
#pragma unroll
        for (int j = 0; j < 4; j++) cs[j] = dc[c0 + j];
    }
#pragma unroll
    for (int i = 0; i < 4; i++)
#pragma unroll
        for (int j = 0; j < 4; j++)
            C[(r0 + i) * MSTR + (c0 + j)] = acc[i][j] * rs[i] * cs[j];
}

// In-place Cholesky of SPD 64x64: A -> L (lower), strict upper zeroed.
__device__ void chol64(float* __restrict__ A) {
    const int tid = threadIdx.x;
    for (int j = 0; j < 64; j++) {
        float ajj = A[j * MSTR + j];
        __syncthreads();
        float d = rsqrtf(fmaxf(ajj, 1e-12f));
        for (int i = j + tid; i < 64; i += TPB) A[i * MSTR + j] *= d;
        __syncthreads();
        int m = 63 - j;
        for (int idx = tid; idx < m * m; idx += TPB) {
            int i = j + 1 + idx / m, k = j + 1 + idx % m;
            A[i * MSTR + k] -= A[i * MSTR + j] * A[k * MSTR + j];
        }
        __syncthreads();
    }
    for (int id = tid; id < 64 * 64; id += TPB) {
        int i = id >> 6, jj = id & 63;
        if (jj > i) A[i * MSTR + jj] = 0.f;
    }
    __syncthreads();
}

// One-sided Jacobi SVD on G. Gt rows = columns of G (stride MSTR, left
// intact). Returns Ht (rows = normalized converged columns = Hhat^T,
// stride MSTR, in the idle Bj half). sm->ev[i] = sigma_i.
__device__ const float* jacobi_svd(Smem* sm, const float* __restrict__ Gt) {
    const int tid = threadIdx.x;
    const int g   = tid >> 3;
    const int sub = tid & 7;

    {   // load column pair (g, 63-g) into slot g, buffer 0
        float2* slot = sm->Bj[0] + g * SLOTF2;
#pragma unroll
        for (int i = 0; i < 4; i++) {
            int f = sub + 8 * i;
            slot[f]         = *reinterpret_cast<const float2*>(Gt + g * MSTR + 2 * f);
            slot[COLF2 + f] = *reinterpret_cast<const float2*>(Gt + (63 - g) * MSTR + 2 * f);
        }
    }

    // tournament routing: old p of slot g -> slot g-1 p (g==1 -> slot0 q),
    // old q of slot g -> slot g+1 q (g==31 -> own p)
    int dpS = (g <= 1) ? 0 : g - 1;
    int dpC = (g == 1) ? 1 : 0;
    int dqS = (g == 31) ? 31 : g + 1;
    int dqC = (g == 31) ? 0 : 1;

    float2* srcB[2]; float2* dpB[2]; float2* dqB[2];
#pragma unroll
    for (int b = 0; b < 2; b++) {
        srcB[b] = sm->Bj[b] + g * SLOTF2;
        dpB[b]  = sm->Bj[b] + dpS * SLOTF2 + dpC * COLF2;
        dqB[b]  = sm->Bj[b] + dqS * SLOTF2 + dqC * COLF2;
    }
    __syncthreads();

    int par = 0;
    float maxr = 0.f;
    for (int sweep = 0; sweep < 10; sweep++) {
        for (int r = 0; r < 63; r++) {
            const float2* s2 = srcB[par];
            float2 bp[4], bq[4];
#pragma unroll
            for (int i = 0; i < 4; i++) {
                bp[i] = s2[sub + 8 * i];
                bq[i] = s2[COLF2 + sub + 8 * i];
            }
            float2 dpp = {0.f, 0.f}, dqq = {0.f, 0.f}, dpq = {0.f, 0.f};
#pragma unroll
            for (int i = 0; i < 4; i++) {
                dpp = ffma2(bp[i], bp[i], dpp);
                dqq = ffma2(bq[i], bq[i], dqq);
                dpq = ffma2(bp[i], bq[i], dpq);
            }
            float pp = dpp.x + dpp.y, qq = dqq.x + dqq.y, pq = dpq.x + dpq.y;
#pragma unroll
            for (int o = 1; o < 8; o <<= 1) {
                pp += __shfl_xor_sync(0xffffffffu, pp, o);
                qq += __shfl_xor_sync(0xffffffffu, qq, o);
                pq += __shfl_xor_sync(0xffffffffu, pq, o);
            }
            float denom = pp * qq + 1e-30f;
            float pq2 = pq * pq;
            maxr = fmaxf(maxr, pq2 / denom);

            float c = 1.f, sv = 0.f;
            if (pq2 > 1e-28f * denom) {
                float th = (qq - pp) / (2.f * pq);
                float t  = 1.f / (fabsf(th) + sqrtf(th * th + 1.f));
                t = copysignf(t, th);
                c  = rsqrtf(1.f + t * t);
                sv = t * c;
            }
            float2 c2  = {c, c}, s2v = {sv, sv}, ns2 = {-sv, -sv};
            float2* dp = dpB[par ^ 1];
            float2* dq = dqB[par ^ 1];
#pragma unroll
            for (int i = 0; i < 4; i++) {
                int f = sub + 8 * i;
                dp[f] = ffma2(bp[i], c2,  fmul2(bq[i], ns2));
                dq[f] = ffma2(bp[i], s2v, fmul2(bq[i], c2));
            }
            par ^= 1;
            __syncthreads();
        }
        float v = maxr;
#pragma unroll
        for (int o = 16; o; o >>= 1)
            v = fmaxf(v, __shfl_xor_sync(0xffffffffu, v, o));
        if ((tid & 31) == 0) sm->red[tid >> 5] = v;
        __syncthreads();
        if (tid == 0) {
            float m = 0.f;
            for (int w = 0; w < 8; w++) m = fmaxf(m, sm->red[w]);
            sm->red[8] = m;
        }
        __syncthreads();
        if (sm->red[8] < 1e-12f) break;
        maxr = 0.f;
    }

    // extraction: sigma = ||col||, Ht rows = col/sigma (idle buffer half)
    float* Ht = reinterpret_cast<float*>(sm->Bj[par ^ 1]);
    {
        const float2* s2 = srcB[par];
        float2 bp[4], bq[4];
#pragma unroll
        for (int i = 0; i < 4; i++) {
            bp[i] = s2[sub + 8 * i];
            bq[i] = s2[COLF2 + sub + 8 * i];
        }
        float2 dpp = {0.f, 0.f}, dqq = {0.f, 0.f};
#pragma unroll
        for (int i = 0; i < 4; i++) {
            dpp = ffma2(bp[i], bp[i], dpp);
            dqq = ffma2(bq[i], bq[i], dqq);
        }
        float pp = dpp.x + dpp.y, qq = dqq.x + dqq.y;
#pragma unroll
        for (int o = 1; o < 8; o <<= 1) {
            pp += __shfl_xor_sync(0xffffffffu, pp, o);
            qq += __shfl_xor_sync(0xffffffffu, qq, o);
        }
        float inp = rsqrtf(fmaxf(pp, 1e-30f));
        float inq = rsqrtf(fmaxf(qq, 1e-30f));
        float* rowP = Ht + (2 * g) * MSTR;
        float* rowQ = Ht + (2 * g + 1) * MSTR;
#pragma unroll
        for (int i = 0; i < 4; i++) {
            int f = sub + 8 * i;
            float2 vp = {bp[i].x * inp, bp[i].y * inp};
            float2 vq = {bq[i].x * inq, bq[i].y * inq};
            *reinterpret_cast<float2*>(rowP + 2 * f) = vp;
            *reinterpret_cast<float2*>(rowQ + 2 * f) = vq;
        }
        if (sub == 0) {
            sm->ev[2 * g]     = pp * inp;   // sqrt(pp) = sigma_p
            sm->ev[2 * g + 1] = qq * inq;
        }
    }
    __syncthreads();
    return Ht;
}

__global__ void __launch_bounds__(TPB, 2)
spd_frechet_kernel(const float* __restrict__ x, const float* __restrict__ wm,
                   float* __restrict__ out) {
    extern __shared__ __align__(16) char smem_raw[];
    Smem* sm = reinterpret_cast<Smem*>(smem_raw);
    const int b = blockIdx.x;
    const int tid = threadIdx.x;

    if (tid == 0) {
        float cum = 0.f;
        for (int n = 0; n < 16; n++) {
            float w = wm[n] * wm[n];
            cum += w;
            sm->tvals[n] = w / cum;
        }
    }

    const float* xb = x + (size_t)b * 16 * 4096;

    // Ft0 = chol(x[b,0]): stored L rows = columns of F = L^T, M0 = F^T F = x0.
    load_mat64(xb, sm->M0);
    __syncthreads();
    chol64(sm->M0);

    for (int n = 1; n < 16; n++) {
        // eigh(M) via SVD of F
        const float* Ht1 = jacobi_svd(sm, sm->M0);
        if (tid < 64) {
            float s = sm->ev[tid];
            sm->isig[tid] = 1.f / fmaxf(s, 1e-20f);
            float es = fmaxf(s, 1e-5f);       // = sqrt(max(lambda,1e-10))
            sm->es[tid]  = es;
            sm->eis[tid] = 1.f / es;
        }
        __syncthreads();
        // Vt = diag(1/sigma) Ht1 Ft^T
        mm64<0, 1, 0, 1, 0>(Ht1, sm->M0, sm->M1, nullptr, sm->isig, nullptr);
        __syncthreads();

        // L = chol(X_n)
        load_mat64(xb + (size_t)n * 4096, sm->M2);
        __syncthreads();
        chol64(sm->M2);

        // Ct = diag(eis) Vt L     (S' = C^T C)
        mm64<0, 0, 0, 1, 0>(sm->M1, sm->M2, sm->M3, nullptr, sm->eis, nullptr);
        __syncthreads();

        // eigh(S') via SVD of C
        const float* Ht2 = jacobi_svd(sm, sm->M3);
        float tn = sm->tvals[n];
        if (tid < 64) {
            float tau = sm->ev[tid];
            sm->itau[tid] = 1.f / fmaxf(tau, 1e-20f);
            float f = fmaxf(tau * tau, 1e-10f);
            sm->ft2[tid] = exp2f(0.5f * tn * log2f(f));   // f^{t/2}
        }
        __syncthreads();
        // U't = diag(1/tau) Ht2 Ct^T
        mm64<0, 1, 0, 1, 0>(Ht2, sm->M3, sm->M2, nullptr, sm->itau, nullptr);
        __syncthreads();
        // Ft' = V diag(es) U' diag(f^{t/2})
        //   C[r][c] = sum_k Vt[k][r] * es[k] * U't[c][k] * ft2[c]
        mm64<1, 1, 1, 0, 1>(sm->M1, sm->M2, sm->M0, sm->es, nullptr, sm->ft2);
        __syncthreads();
    }

    // M = Ft Ft^T
    mm64<0, 1, 0, 0, 0>(sm->M0, sm->M0, sm->M1, nullptr, nullptr, nullptr);
    __syncthreads();

    float* ob = out + (size_t)b * 4096;
    for (int id = tid; id < 2048; id += TPB) {
        int i = id >> 5, jj = id & 31;
        reinterpret_cast<float2*>(ob)[id] =
            reinterpret_cast<const float2*>(sm->M1 + i * MSTR)[jj];
    }
}

extern "C" void kernel_launch(void* const* d_in, const int* in_sizes, int n_in,
                              void* d_out, int out_size) {
    (void)in_sizes; (void)n_in; (void)out_size;
    const float* x  = (const float*)d_in[0];
    const float* wm = (const float*)d_in[1];
    float* out = (float*)d_out;

    int smem = (int)sizeof(Smem);
    cudaFuncSetAttribute(spd_frechet_kernel,
                         cudaFuncAttributeMaxDynamicSharedMemorySize, smem);
    spd_frechet_kernel<<<512, TPB, smem>>>(x, wm, out);
}